// round 4
// baseline (speedup 1.0000x reference)
#include <cuda_runtime.h>
#include <cstdint>

#define NP 500000
#define NB 20000
#define NC 5000
#define NS 2000
#define NTOT 527000
#define NE 500000
#define EDIR (3 * NE * 2)
#define H 64
#define FIN 384

#define SCAN_SPAN 2048
#define NBLK_SCAN ((NTOT + SCAN_SPAN - 1) / SCAN_SPAN)

// ---------------- scratch ----------------------------------------------------
__device__ float g_x[(size_t)NTOT * H];
__device__ float g_h[(size_t)NTOT * H];
__device__ int   g_deg[NTOT];
__device__ int   g_rowstart[NTOT];
__device__ int   g_cursor[NTOT];
__device__ int   g_scaninc[NTOT];
__device__ int   g_blocksum[512];
__device__ int   g_adj[EDIR];

// ---------------- tf32 helpers ----------------------------------------------
__device__ __forceinline__ uint32_t f2tf(float x) {
    uint32_t r;
    asm("cvt.rna.tf32.f32 %0, %1;" : "=r"(r) : "f"(x));
    return r;
}
__device__ __forceinline__ void mma_tf32(float* d, uint32_t a0, uint32_t a1,
                                         uint32_t a2, uint32_t a3,
                                         uint32_t b0, uint32_t b1) {
    asm volatile(
        "mma.sync.aligned.m16n8k8.row.col.f32.tf32.tf32.f32 "
        "{%0,%1,%2,%3},{%4,%5,%6,%7},{%8,%9},{%0,%1,%2,%3};"
        : "+f"(d[0]), "+f"(d[1]), "+f"(d[2]), "+f"(d[3])
        : "r"(a0), "r"(a1), "r"(a2), "r"(a3), "r"(b0), "r"(b1));
}

// ---------------- CSR build ---------------------------------------------------
__global__ void __launch_bounds__(256) zero_deg() {
    int i = blockIdx.x * 256 + threadIdx.x;
    if (i < NTOT) g_deg[i] = 0;
}

__global__ void __launch_bounds__(256) hist_edges(
    const int* __restrict__ pb_src, const int* __restrict__ pb_dst,
    const int* __restrict__ pc_src, const int* __restrict__ pc_dst,
    const int* __restrict__ ps_src, const int* __restrict__ ps_dst) {
    int e = blockIdx.x * 256 + threadIdx.x;
    if (e >= 3 * NE) return;
    int t = e / NE, i = e - t * NE;
    const int* sp; const int* dp; int off;
    if (t == 0)      { sp = pb_src; dp = pb_dst; off = NP; }
    else if (t == 1) { sp = pc_src; dp = pc_dst; off = NP + NB; }
    else             { sp = ps_src; dp = ps_dst; off = NP + NB + NC; }
    int p = __ldg(sp + i);
    int o = __ldg(dp + i) + off;
    atomicAdd(&g_deg[p], 1);
    atomicAdd(&g_deg[o], 1);
}

__global__ void __launch_bounds__(256) scanA() {
    __shared__ int wsum[8];
    __shared__ int wpre[8];
    int tid = threadIdx.x, lane = tid & 31, wid = tid >> 5;
    int base = blockIdx.x * SCAN_SPAN + tid * 8;
    int v[8], run = 0;
#pragma unroll
    for (int t = 0; t < 8; t++) {
        int idx = base + t;
        int d = (idx < NTOT) ? g_deg[idx] : 0;
        run += d;
        v[t] = run;
    }
    int tot = run;
#pragma unroll
    for (int off = 1; off < 32; off <<= 1) {
        int n = __shfl_up_sync(0xffffffffu, tot, off);
        if (lane >= off) tot += n;
    }
    int wexcl = tot - run;
    if (lane == 31) wsum[wid] = tot;
    __syncthreads();
    if (tid < 8) {
        int s = wsum[tid];
        int r = s;
#pragma unroll
        for (int off = 1; off < 8; off <<= 1) {
            int n = __shfl_up_sync(0xffu, r, off);
            if (tid >= off) r += n;
        }
        wpre[tid] = r - s;
        if (tid == 7) g_blocksum[blockIdx.x] = r;
    }
    __syncthreads();
    int bexcl = wexcl + wpre[wid];
#pragma unroll
    for (int t = 0; t < 8; t++) {
        int idx = base + t;
        if (idx < NTOT) g_scaninc[idx] = v[t] + bexcl;
    }
}

__global__ void __launch_bounds__(512) scanB() {
    __shared__ int s[NBLK_SCAN];
    int tid = threadIdx.x;
    if (tid < NBLK_SCAN) s[tid] = g_blocksum[tid];
    __syncthreads();
    if (tid == 0) {
        int run = 0;
        for (int i = 0; i < NBLK_SCAN; i++) { int t = s[i]; s[i] = run; run += t; }
    }
    __syncthreads();
    if (tid < NBLK_SCAN) g_blocksum[tid] = s[tid];
}

__global__ void __launch_bounds__(256) scanC() {
    int i = blockIdx.x * 256 + threadIdx.x;
    if (i >= NTOT) return;
    int start = g_scaninc[i] + g_blocksum[i >> 11] - g_deg[i];
    g_rowstart[i] = start;
    g_cursor[i] = start;
}

__global__ void __launch_bounds__(256) fill_csr(
    const int* __restrict__ pb_src, const int* __restrict__ pb_dst,
    const int* __restrict__ pc_src, const int* __restrict__ pc_dst,
    const int* __restrict__ ps_src, const int* __restrict__ ps_dst) {
    int e = blockIdx.x * 256 + threadIdx.x;
    if (e >= 3 * NE) return;
    int t = e / NE, i = e - t * NE;
    const int* sp; const int* dp; int off;
    if (t == 0)      { sp = pb_src; dp = pb_dst; off = NP; }
    else if (t == 1) { sp = pc_src; dp = pc_dst; off = NP + NB; }
    else             { sp = ps_src; dp = ps_dst; off = NP + NB + NC; }
    int p = __ldg(sp + i);
    int o = __ldg(dp + i) + off;
    int pos = atomicAdd(&g_cursor[o], 1);
    g_adj[pos] = p;
    int pos2 = atomicAdd(&g_cursor[p], 1);
    g_adj[pos2] = o;
}

// ---------------- feature assembly --------------------------------------------
__global__ void __launch_bounds__(256) copy_emb(const float* __restrict__ eb,
                                                const float* __restrict__ ec,
                                                const float* __restrict__ es) {
    int i = blockIdx.x * 256 + threadIdx.x;
    const int tot = (NB + NC + NS) * H / 4;
    if (i >= tot) return;
    const int nb4 = NB * H / 4, nc4 = NC * H / 4;
    float4 v;
    if (i < nb4) v = reinterpret_cast<const float4*>(eb)[i];
    else if (i < nb4 + nc4) v = reinterpret_cast<const float4*>(ec)[i - nb4];
    else v = reinterpret_cast<const float4*>(es)[i - nb4 - nc4];
    reinterpret_cast<float4*>(g_x)[(size_t)NP * H / 4 + i] = v;
}

// ---------------- proj: relu(x_product @ W_proj^T + b) via tf32 HMMA ----------
__global__ void __launch_bounds__(256) proj_tc(const float* __restrict__ A,
                                               const float* __restrict__ W,
                                               const float* __restrict__ bias) {
    __shared__ uint32_t As[128][20];
    __shared__ uint32_t Ws[64][20];
    const int tid = threadIdx.x;
    const int m0 = blockIdx.x * 128;
    const int warp = tid >> 5, lane = tid & 31;
    const int g = lane >> 2, t = lane & 3;

    float acc[8][4];
#pragma unroll
    for (int j = 0; j < 8; j++)
#pragma unroll
        for (int c = 0; c < 4; c++) acc[j][c] = 0.f;

    for (int kb = 0; kb < FIN; kb += 16) {
#pragma unroll
        for (int q = 0; q < 2; q++) {
            int idx = tid + 256 * q;
            int row = idx >> 2, c4 = idx & 3;
            int rg = m0 + row; if (rg > NP - 1) rg = NP - 1;
            float4 v = *reinterpret_cast<const float4*>(A + (size_t)rg * FIN + kb + c4 * 4);
            uint4 u = make_uint4(f2tf(v.x), f2tf(v.y), f2tf(v.z), f2tf(v.w));
            *reinterpret_cast<uint4*>(&As[row][c4 * 4]) = u;
        }
        {
            int n = tid >> 2, c4 = tid & 3;
            float4 v = *reinterpret_cast<const float4*>(W + (size_t)n * FIN + kb + c4 * 4);
            uint4 u = make_uint4(f2tf(v.x), f2tf(v.y), f2tf(v.z), f2tf(v.w));
            *reinterpret_cast<uint4*>(&Ws[n][c4 * 4]) = u;
        }
        __syncthreads();
        const int r0 = warp * 16;
#pragma unroll
        for (int ks = 0; ks < 2; ks++) {
            int k0 = ks * 8;
            uint32_t a0 = As[r0 + g][k0 + t];
            uint32_t a1 = As[r0 + g + 8][k0 + t];
            uint32_t a2 = As[r0 + g][k0 + t + 4];
            uint32_t a3 = As[r0 + g + 8][k0 + t + 4];
#pragma unroll
            for (int j = 0; j < 8; j++) {
                uint32_t b0 = Ws[j * 8 + g][k0 + t];
                uint32_t b1 = Ws[j * 8 + g][k0 + t + 4];
                mma_tf32(acc[j], a0, a1, a2, a3, b0, b1);
            }
        }
        __syncthreads();
    }
#pragma unroll
    for (int j = 0; j < 8; j++) {
        int col = j * 8 + 2 * t;
        float b0 = bias[col], b1 = bias[col + 1];
        int r1 = m0 + warp * 16 + g;
        if (r1 < NP) {
            float2 o = make_float2(fmaxf(acc[j][0] + b0, 0.f), fmaxf(acc[j][1] + b1, 0.f));
            *reinterpret_cast<float2*>(g_x + (size_t)r1 * H + col) = o;
        }
        int r2 = r1 + 8;
        if (r2 < NP) {
            float2 o = make_float2(fmaxf(acc[j][2] + b0, 0.f), fmaxf(acc[j][3] + b1, 0.f));
            *reinterpret_cast<float2*>(g_x + (size_t)r2 * H + col) = o;
        }
    }
}

// ---------------- fused SAGE layer: gather-mean + dual GEMM -------------------
// C[tile] = mean_agg(tile) @ Wl^T + x[tile] @ Wr^T + b, optional relu.
// One 128-row tile per block. smem buffer is reused: pass 1 = agg, pass 2 = self.
// Blocks are reversed so heavy-degree nodes (high ids) are scheduled first.
template <int NOUT, bool RELU, bool USEH>
__global__ void __launch_bounds__(256) fused_layer(const float* __restrict__ Wr,
                                                   const float* __restrict__ Wl,
                                                   const float* __restrict__ bias,
                                                   float* __restrict__ outp) {
    constexpr int NT = NOUT / 8;
    extern __shared__ uint32_t smem[];
    uint32_t (*buf)[68] = reinterpret_cast<uint32_t(*)[68]>(smem);           // [128][68]
    uint32_t (*wrS)[68] = reinterpret_cast<uint32_t(*)[68]>(smem + 128 * 68);
    uint32_t (*wlS)[68] = reinterpret_cast<uint32_t(*)[68]>(smem + (128 + NOUT) * 68);

    const int tid = threadIdx.x;
    const int row0 = ((int)gridDim.x - 1 - (int)blockIdx.x) * 128;
    const int warp = tid >> 5, lane = tid & 31;
    const int g = lane >> 2, t = lane & 3;
    const float* xsrc = USEH ? g_h : g_x;
    float* out = (NOUT == H) ? g_h : outp;

    // load both weight matrices (tf32)
    for (int idx = tid; idx < NOUT * 16; idx += 256) {
        int n = idx >> 4, c4 = idx & 15;
        float4 v = *reinterpret_cast<const float4*>(Wr + (size_t)n * H + c4 * 4);
        *reinterpret_cast<uint4*>(&wrS[n][c4 * 4]) =
            make_uint4(f2tf(v.x), f2tf(v.y), f2tf(v.z), f2tf(v.w));
        float4 w = *reinterpret_cast<const float4*>(Wl + (size_t)n * H + c4 * 4);
        *reinterpret_cast<uint4*>(&wlS[n][c4 * 4]) =
            make_uint4(f2tf(w.x), f2tf(w.y), f2tf(w.z), f2tf(w.w));
    }

    float acc[NT][4];
#pragma unroll
    for (int j = 0; j < NT; j++)
#pragma unroll
        for (int c = 0; c < 4; c++) acc[j][c] = 0.f;

    // ---- pass 1: gather-mean into buf (one warp per row, 16 rows/warp) ----
    {
        int half = lane >> 4;
        int f = (lane & 15) * 4;
        for (int i = 0; i < 16; i++) {
            int il = warp * 16 + i;
            int n = row0 + il;
            if (n >= NTOT) break;
            int start = g_rowstart[n];
            int deg = g_deg[n];
            float4 a = make_float4(0.f, 0.f, 0.f, 0.f);
            for (int it = 0; 2 * it + half < deg; it++) {
                int s = __ldg(g_adj + start + 2 * it + half);
                float4 v = *reinterpret_cast<const float4*>(xsrc + (size_t)s * H + f);
                a.x += v.x; a.y += v.y; a.z += v.z; a.w += v.w;
            }
            a.x += __shfl_xor_sync(0xffffffffu, a.x, 16);
            a.y += __shfl_xor_sync(0xffffffffu, a.y, 16);
            a.z += __shfl_xor_sync(0xffffffffu, a.z, 16);
            a.w += __shfl_xor_sync(0xffffffffu, a.w, 16);
            if (lane < 16) {
                float inv = 1.f / fmaxf((float)deg, 1.f);
                *reinterpret_cast<uint4*>(&buf[il][f]) =
                    make_uint4(f2tf(a.x * inv), f2tf(a.y * inv),
                               f2tf(a.z * inv), f2tf(a.w * inv));
            }
        }
    }
    __syncthreads();
    // ---- MMA: agg @ Wl^T ----
    {
        const int r0 = warp * 16;
#pragma unroll
        for (int ks = 0; ks < 8; ks++) {
            int k0 = ks * 8;
            uint32_t a0 = buf[r0 + g][k0 + t];
            uint32_t a1 = buf[r0 + g + 8][k0 + t];
            uint32_t a2 = buf[r0 + g][k0 + t + 4];
            uint32_t a3 = buf[r0 + g + 8][k0 + t + 4];
#pragma unroll
            for (int j = 0; j < NT; j++) {
                uint32_t b0 = wlS[j * 8 + g][k0 + t];
                uint32_t b1 = wlS[j * 8 + g][k0 + t + 4];
                mma_tf32(acc[j], a0, a1, a2, a3, b0, b1);
            }
        }
    }
    __syncthreads();
    // ---- pass 2: self rows into buf ----
#pragma unroll
    for (int q = 0; q < 8; q++) {
        int idx = tid + 256 * q;            // 0..2047
        int row = idx >> 4, c4 = idx & 15;
        int n = row0 + row; if (n > NTOT - 1) n = NTOT - 1;
        float4 v = *reinterpret_cast<const float4*>(xsrc + (size_t)n * H + c4 * 4);
        *reinterpret_cast<uint4*>(&buf[row][c4 * 4]) =
            make_uint4(f2tf(v.x), f2tf(v.y), f2tf(v.z), f2tf(v.w));
    }
    __syncthreads();
    // ---- MMA: x @ Wr^T ----
    {
        const int r0 = warp * 16;
#pragma unroll
        for (int ks = 0; ks < 8; ks++) {
            int k0 = ks * 8;
            uint32_t a0 = buf[r0 + g][k0 + t];
            uint32_t a1 = buf[r0 + g + 8][k0 + t];
            uint32_t a2 = buf[r0 + g][k0 + t + 4];
            uint32_t a3 = buf[r0 + g + 8][k0 + t + 4];
#pragma unroll
            for (int j = 0; j < NT; j++) {
                uint32_t b0 = wrS[j * 8 + g][k0 + t];
                uint32_t b1 = wrS[j * 8 + g][k0 + t + 4];
                mma_tf32(acc[j], a0, a1, a2, a3, b0, b1);
            }
        }
    }
    // ---- epilogue ----
#pragma unroll
    for (int j = 0; j < NT; j++) {
        int col = j * 8 + 2 * t;
        float b0 = bias[col], b1 = bias[col + 1];
        int r1 = row0 + warp * 16 + g;
        if (r1 < NTOT) {
            float v0 = acc[j][0] + b0, v1 = acc[j][1] + b1;
            if (RELU) { v0 = fmaxf(v0, 0.f); v1 = fmaxf(v1, 0.f); }
            *reinterpret_cast<float2*>(out + (size_t)r1 * NOUT + col) = make_float2(v0, v1);
        }
        int r2 = r1 + 8;
        if (r2 < NTOT) {
            float v2 = acc[j][2] + b0, v3 = acc[j][3] + b1;
            if (RELU) { v2 = fmaxf(v2, 0.f); v3 = fmaxf(v3, 0.f); }
            *reinterpret_cast<float2*>(out + (size_t)r2 * NOUT + col) = make_float2(v2, v3);
        }
    }
}

// ---------------- launch -------------------------------------------------------
extern "C" void kernel_launch(void* const* d_in, const int* in_sizes, int n_in,
                              void* d_out, int out_size) {
    const float* x_product = (const float*)d_in[0];
    const int* pb_src = (const int*)d_in[1];
    const int* pb_dst = (const int*)d_in[2];
    const int* pc_src = (const int*)d_in[3];
    const int* pc_dst = (const int*)d_in[4];
    const int* ps_src = (const int*)d_in[5];
    const int* ps_dst = (const int*)d_in[6];
    const float* W_proj = (const float*)d_in[7];
    const float* b_proj = (const float*)d_in[8];
    const float* emb_brand = (const float*)d_in[9];
    const float* emb_cat = (const float*)d_in[10];
    const float* emb_shop = (const float*)d_in[11];
    const float* W1_l = (const float*)d_in[12];
    const float* b1_l = (const float*)d_in[13];
    const float* W1_r = (const float*)d_in[14];
    const float* W2_l = (const float*)d_in[15];
    const float* b2_l = (const float*)d_in[16];
    const float* W2_r = (const float*)d_in[17];
    float* out = (float*)d_out;

    const int nodeBlocks = (NTOT + 255) / 256;
    const int edgeBlocks = (3 * NE + 255) / 256;
    const int gemmBlocks = (NTOT + 127) / 128;

    const int smem1 = (128 + 2 * 64) * 68 * 4;   // 69632
    const int smem2 = (128 + 2 * 32) * 68 * 4;   // 52224
    cudaFuncSetAttribute(fused_layer<64, true, false>,
                         cudaFuncAttributeMaxDynamicSharedMemorySize, smem1);
    cudaFuncSetAttribute(fused_layer<32, false, true>,
                         cudaFuncAttributeMaxDynamicSharedMemorySize, smem2);

    // --- build CSR once ---
    zero_deg<<<nodeBlocks, 256>>>();
    hist_edges<<<edgeBlocks, 256>>>(pb_src, pb_dst, pc_src, pc_dst, ps_src, ps_dst);
    scanA<<<NBLK_SCAN, 256>>>();
    scanB<<<1, 512>>>();
    scanC<<<nodeBlocks, 256>>>();
    fill_csr<<<edgeBlocks, 256>>>(pb_src, pb_dst, pc_src, pc_dst, ps_src, ps_dst);

    // --- node feature assembly ---
    proj_tc<<<(NP + 127) / 128, 256>>>(x_product, W_proj, b_proj);
    copy_emb<<<((NB + NC + NS) * H / 4 + 255) / 256, 256>>>(emb_brand, emb_cat, emb_shop);

    // --- layer 1 (fused gather + GEMM) ---
    fused_layer<64, true, false><<<gemmBlocks, 256, smem1>>>(W1_r, W1_l, b1_l, out);
    // --- layer 2 ---
    fused_layer<32, false, true><<<gemmBlocks, 256, smem2>>>(W2_r, W2_l, b2_l, out);
}

// round 5
// speedup vs baseline: 1.6455x; 1.6455x over previous
#include <cuda_runtime.h>
#include <cstdint>

#define NP 500000
#define NB 20000
#define NC 5000
#define NS 2000
#define NTOT 527000
#define NE 500000
#define EDIR (3 * NE * 2)
#define H 64
#define FIN 384

#define SCAN_SPAN 2048
#define NBLK_SCAN ((NTOT + SCAN_SPAN - 1) / SCAN_SPAN)

// ---------------- scratch ----------------------------------------------------
__device__ float g_x[(size_t)NTOT * H];
__device__ float g_h[(size_t)NTOT * H];
__device__ float g_agg[(size_t)NTOT * H];
__device__ int   g_deg[NTOT];
__device__ int   g_rowstart[NTOT];
__device__ int   g_cursor[NTOT];
__device__ int   g_scaninc[NTOT];
__device__ int   g_blocksum[512];
__device__ int   g_adj[EDIR];

// ---------------- tf32 helpers ----------------------------------------------
__device__ __forceinline__ uint32_t f2tf(float x) {
    uint32_t r;
    asm("cvt.rna.tf32.f32 %0, %1;" : "=r"(r) : "f"(x));
    return r;
}
__device__ __forceinline__ void mma_tf32(float* d, uint32_t a0, uint32_t a1,
                                         uint32_t a2, uint32_t a3,
                                         uint32_t b0, uint32_t b1) {
    asm volatile(
        "mma.sync.aligned.m16n8k8.row.col.f32.tf32.tf32.f32 "
        "{%0,%1,%2,%3},{%4,%5,%6,%7},{%8,%9},{%0,%1,%2,%3};"
        : "+f"(d[0]), "+f"(d[1]), "+f"(d[2]), "+f"(d[3])
        : "r"(a0), "r"(a1), "r"(a2), "r"(a3), "r"(b0), "r"(b1));
}

// ---------------- CSR build ---------------------------------------------------
__global__ void __launch_bounds__(256) zero_deg() {
    int i = blockIdx.x * 256 + threadIdx.x;
    if (i < NTOT) g_deg[i] = 0;
}

__global__ void __launch_bounds__(256) hist_edges(
    const int* __restrict__ pb_src, const int* __restrict__ pb_dst,
    const int* __restrict__ pc_src, const int* __restrict__ pc_dst,
    const int* __restrict__ ps_src, const int* __restrict__ ps_dst) {
    int e = blockIdx.x * 256 + threadIdx.x;
    if (e >= 3 * NE) return;
    int t = e / NE, i = e - t * NE;
    const int* sp; const int* dp; int off;
    if (t == 0)      { sp = pb_src; dp = pb_dst; off = NP; }
    else if (t == 1) { sp = pc_src; dp = pc_dst; off = NP + NB; }
    else             { sp = ps_src; dp = ps_dst; off = NP + NB + NC; }
    int p = __ldg(sp + i);
    int o = __ldg(dp + i) + off;
    atomicAdd(&g_deg[p], 1);
    atomicAdd(&g_deg[o], 1);
}

__global__ void __launch_bounds__(256) scanA() {
    __shared__ int wsum[8];
    __shared__ int wpre[8];
    int tid = threadIdx.x, lane = tid & 31, wid = tid >> 5;
    int base = blockIdx.x * SCAN_SPAN + tid * 8;
    int v[8], run = 0;
#pragma unroll
    for (int t = 0; t < 8; t++) {
        int idx = base + t;
        int d = (idx < NTOT) ? g_deg[idx] : 0;
        run += d;
        v[t] = run;
    }
    int tot = run;
#pragma unroll
    for (int off = 1; off < 32; off <<= 1) {
        int n = __shfl_up_sync(0xffffffffu, tot, off);
        if (lane >= off) tot += n;
    }
    int wexcl = tot - run;
    if (lane == 31) wsum[wid] = tot;
    __syncthreads();
    if (tid < 8) {
        int s = wsum[tid];
        int r = s;
#pragma unroll
        for (int off = 1; off < 8; off <<= 1) {
            int n = __shfl_up_sync(0xffu, r, off);
            if (tid >= off) r += n;
        }
        wpre[tid] = r - s;
        if (tid == 7) g_blocksum[blockIdx.x] = r;
    }
    __syncthreads();
    int bexcl = wexcl + wpre[wid];
#pragma unroll
    for (int t = 0; t < 8; t++) {
        int idx = base + t;
        if (idx < NTOT) g_scaninc[idx] = v[t] + bexcl;
    }
}

__global__ void __launch_bounds__(512) scanB() {
    __shared__ int s[NBLK_SCAN];
    int tid = threadIdx.x;
    if (tid < NBLK_SCAN) s[tid] = g_blocksum[tid];
    __syncthreads();
    if (tid == 0) {
        int run = 0;
        for (int i = 0; i < NBLK_SCAN; i++) { int t = s[i]; s[i] = run; run += t; }
    }
    __syncthreads();
    if (tid < NBLK_SCAN) g_blocksum[tid] = s[tid];
}

__global__ void __launch_bounds__(256) scanC() {
    int i = blockIdx.x * 256 + threadIdx.x;
    if (i >= NTOT) return;
    int start = g_scaninc[i] + g_blocksum[i >> 11] - g_deg[i];
    g_rowstart[i] = start;
    g_cursor[i] = start;
}

__global__ void __launch_bounds__(256) fill_csr(
    const int* __restrict__ pb_src, const int* __restrict__ pb_dst,
    const int* __restrict__ pc_src, const int* __restrict__ pc_dst,
    const int* __restrict__ ps_src, const int* __restrict__ ps_dst) {
    int e = blockIdx.x * 256 + threadIdx.x;
    if (e >= 3 * NE) return;
    int t = e / NE, i = e - t * NE;
    const int* sp; const int* dp; int off;
    if (t == 0)      { sp = pb_src; dp = pb_dst; off = NP; }
    else if (t == 1) { sp = pc_src; dp = pc_dst; off = NP + NB; }
    else             { sp = ps_src; dp = ps_dst; off = NP + NB + NC; }
    int p = __ldg(sp + i);
    int o = __ldg(dp + i) + off;
    int pos = atomicAdd(&g_cursor[o], 1);
    g_adj[pos] = p;
    int pos2 = atomicAdd(&g_cursor[p], 1);
    g_adj[pos2] = o;
}

// ---------------- feature assembly --------------------------------------------
__global__ void __launch_bounds__(256) copy_emb(const float* __restrict__ eb,
                                                const float* __restrict__ ec,
                                                const float* __restrict__ es) {
    int i = blockIdx.x * 256 + threadIdx.x;
    const int tot = (NB + NC + NS) * H / 4;
    if (i >= tot) return;
    const int nb4 = NB * H / 4, nc4 = NC * H / 4;
    float4 v;
    if (i < nb4) v = reinterpret_cast<const float4*>(eb)[i];
    else if (i < nb4 + nc4) v = reinterpret_cast<const float4*>(ec)[i - nb4];
    else v = reinterpret_cast<const float4*>(es)[i - nb4 - nc4];
    reinterpret_cast<float4*>(g_x)[(size_t)NP * H / 4 + i] = v;
}

// ---------------- proj: relu(x_product @ W_proj^T + b) via tf32 HMMA ----------
__global__ void __launch_bounds__(256) proj_tc(const float* __restrict__ A,
                                               const float* __restrict__ W,
                                               const float* __restrict__ bias) {
    __shared__ uint32_t As[128][20];
    __shared__ uint32_t Ws[64][20];
    const int tid = threadIdx.x;
    const int m0 = blockIdx.x * 128;
    const int warp = tid >> 5, lane = tid & 31;
    const int g = lane >> 2, t = lane & 3;

    float acc[8][4];
#pragma unroll
    for (int j = 0; j < 8; j++)
#pragma unroll
        for (int c = 0; c < 4; c++) acc[j][c] = 0.f;

    for (int kb = 0; kb < FIN; kb += 16) {
#pragma unroll
        for (int q = 0; q < 2; q++) {
            int idx = tid + 256 * q;
            int row = idx >> 2, c4 = idx & 3;
            int rg = m0 + row; if (rg > NP - 1) rg = NP - 1;
            float4 v = *reinterpret_cast<const float4*>(A + (size_t)rg * FIN + kb + c4 * 4);
            uint4 u = make_uint4(f2tf(v.x), f2tf(v.y), f2tf(v.z), f2tf(v.w));
            *reinterpret_cast<uint4*>(&As[row][c4 * 4]) = u;
        }
        {
            int n = tid >> 2, c4 = tid & 3;
            float4 v = *reinterpret_cast<const float4*>(W + (size_t)n * FIN + kb + c4 * 4);
            uint4 u = make_uint4(f2tf(v.x), f2tf(v.y), f2tf(v.z), f2tf(v.w));
            *reinterpret_cast<uint4*>(&Ws[n][c4 * 4]) = u;
        }
        __syncthreads();
        const int r0 = warp * 16;
#pragma unroll
        for (int ks = 0; ks < 2; ks++) {
            int k0 = ks * 8;
            uint32_t a0 = As[r0 + g][k0 + t];
            uint32_t a1 = As[r0 + g + 8][k0 + t];
            uint32_t a2 = As[r0 + g][k0 + t + 4];
            uint32_t a3 = As[r0 + g + 8][k0 + t + 4];
#pragma unroll
            for (int j = 0; j < 8; j++) {
                uint32_t b0 = Ws[j * 8 + g][k0 + t];
                uint32_t b1 = Ws[j * 8 + g][k0 + t + 4];
                mma_tf32(acc[j], a0, a1, a2, a3, b0, b1);
            }
        }
        __syncthreads();
    }
#pragma unroll
    for (int j = 0; j < 8; j++) {
        int col = j * 8 + 2 * t;
        float b0 = bias[col], b1 = bias[col + 1];
        int r1 = m0 + warp * 16 + g;
        if (r1 < NP) {
            float2 o = make_float2(fmaxf(acc[j][0] + b0, 0.f), fmaxf(acc[j][1] + b1, 0.f));
            *reinterpret_cast<float2*>(g_x + (size_t)r1 * H + col) = o;
        }
        int r2 = r1 + 8;
        if (r2 < NP) {
            float2 o = make_float2(fmaxf(acc[j][2] + b0, 0.f), fmaxf(acc[j][3] + b1, 0.f));
            *reinterpret_cast<float2*>(g_x + (size_t)r2 * H + col) = o;
        }
    }
}

// ---------------- CSR mean aggregation: one warp per node, MLP-unrolled -------
// Node order reversed so heavy-degree (high-id) nodes schedule first.
__global__ void __launch_bounds__(256) aggregate(int use_h) {
    int gw = (blockIdx.x * 256 + threadIdx.x) >> 5;
    if (gw >= NTOT) return;
    int node = NTOT - 1 - gw;
    int lane = threadIdx.x & 31;
    int start = g_rowstart[node];
    int deg = g_deg[node];
    const float* __restrict__ x = use_h ? g_h : g_x;
    int half = lane >> 4;                 // 0 or 1
    int f = (lane & 15) * 4;
    // two independent accumulator chains: neighbors (i) and (i+2) in flight
    float4 acc0 = make_float4(0.f, 0.f, 0.f, 0.f);
    float4 acc1 = make_float4(0.f, 0.f, 0.f, 0.f);
    int i = half;
    for (; i + 2 < deg; i += 4) {
        int s0 = __ldg(g_adj + start + i);
        int s1 = __ldg(g_adj + start + i + 2);
        float4 v0 = *reinterpret_cast<const float4*>(x + (size_t)s0 * H + f);
        float4 v1 = *reinterpret_cast<const float4*>(x + (size_t)s1 * H + f);
        acc0.x += v0.x; acc0.y += v0.y; acc0.z += v0.z; acc0.w += v0.w;
        acc1.x += v1.x; acc1.y += v1.y; acc1.z += v1.z; acc1.w += v1.w;
    }
    if (i < deg) {
        int s0 = __ldg(g_adj + start + i);
        float4 v0 = *reinterpret_cast<const float4*>(x + (size_t)s0 * H + f);
        acc0.x += v0.x; acc0.y += v0.y; acc0.z += v0.z; acc0.w += v0.w;
    }
    acc0.x += acc1.x; acc0.y += acc1.y; acc0.z += acc1.z; acc0.w += acc1.w;
    acc0.x += __shfl_xor_sync(0xffffffffu, acc0.x, 16);
    acc0.y += __shfl_xor_sync(0xffffffffu, acc0.y, 16);
    acc0.z += __shfl_xor_sync(0xffffffffu, acc0.z, 16);
    acc0.w += __shfl_xor_sync(0xffffffffu, acc0.w, 16);
    if (lane < 16) {
        float inv = 1.f / fmaxf((float)deg, 1.f);
        float4 o = make_float4(acc0.x * inv, acc0.y * inv, acc0.z * inv, acc0.w * inv);
        *reinterpret_cast<float4*>(g_agg + (size_t)node * H + f) = o;
    }
}

// ---------------- SAGE finalize via tf32 HMMA ---------------------------------
template <int NOUT, bool RELU, bool USEH>
__global__ void __launch_bounds__(256) finalize_tc(const float* __restrict__ Wr,
                                                   const float* __restrict__ Wl,
                                                   const float* __restrict__ bias,
                                                   float* __restrict__ outp) {
    constexpr int NT = NOUT / 8;
    __shared__ uint32_t As[128][20];
    __shared__ uint32_t Ws[NOUT][20];
    const int tid = threadIdx.x;
    const int m0 = blockIdx.x * 128;
    const int warp = tid >> 5, lane = tid & 31;
    const int g = lane >> 2, t = lane & 3;
    const float* xsrc = USEH ? g_h : g_x;
    float* out = (NOUT == H) ? g_h : outp;

    float acc[NT][4];
#pragma unroll
    for (int j = 0; j < NT; j++)
#pragma unroll
        for (int c = 0; c < 4; c++) acc[j][c] = 0.f;

    for (int kb = 0; kb < 2 * H; kb += 16) {
        const float* src = (kb < H) ? xsrc : g_agg;
        const float* W = (kb < H) ? Wr : Wl;
        const int kcol = kb & (H - 1);
#pragma unroll
        for (int q = 0; q < 2; q++) {
            int idx = tid + 256 * q;
            int row = idx >> 2, c4 = idx & 3;
            int rg = m0 + row; if (rg > NTOT - 1) rg = NTOT - 1;
            float4 v = *reinterpret_cast<const float4*>(src + (size_t)rg * H + kcol + c4 * 4);
            uint4 u = make_uint4(f2tf(v.x), f2tf(v.y), f2tf(v.z), f2tf(v.w));
            *reinterpret_cast<uint4*>(&As[row][c4 * 4]) = u;
        }
        if (tid < NOUT * 4) {
            int n = tid >> 2, c4 = tid & 3;
            float4 v = *reinterpret_cast<const float4*>(W + (size_t)n * H + kcol + c4 * 4);
            uint4 u = make_uint4(f2tf(v.x), f2tf(v.y), f2tf(v.z), f2tf(v.w));
            *reinterpret_cast<uint4*>(&Ws[n][c4 * 4]) = u;
        }
        __syncthreads();
        const int r0 = warp * 16;
#pragma unroll
        for (int ks = 0; ks < 2; ks++) {
            int k0 = ks * 8;
            uint32_t a0 = As[r0 + g][k0 + t];
            uint32_t a1 = As[r0 + g + 8][k0 + t];
            uint32_t a2 = As[r0 + g][k0 + t + 4];
            uint32_t a3 = As[r0 + g + 8][k0 + t + 4];
#pragma unroll
            for (int j = 0; j < NT; j++) {
                uint32_t b0 = Ws[j * 8 + g][k0 + t];
                uint32_t b1 = Ws[j * 8 + g][k0 + t + 4];
                mma_tf32(acc[j], a0, a1, a2, a3, b0, b1);
            }
        }
        __syncthreads();
    }
#pragma unroll
    for (int j = 0; j < NT; j++) {
        int col = j * 8 + 2 * t;
        float b0 = bias[col], b1 = bias[col + 1];
        int r1 = m0 + warp * 16 + g;
        if (r1 < NTOT) {
            float v0 = acc[j][0] + b0, v1 = acc[j][1] + b1;
            if (RELU) { v0 = fmaxf(v0, 0.f); v1 = fmaxf(v1, 0.f); }
            *reinterpret_cast<float2*>(out + (size_t)r1 * NOUT + col) = make_float2(v0, v1);
        }
        int r2 = r1 + 8;
        if (r2 < NTOT) {
            float v2 = acc[j][2] + b0, v3 = acc[j][3] + b1;
            if (RELU) { v2 = fmaxf(v2, 0.f); v3 = fmaxf(v3, 0.f); }
            *reinterpret_cast<float2*>(out + (size_t)r2 * NOUT + col) = make_float2(v2, v3);
        }
    }
}

// ---------------- launch -------------------------------------------------------
extern "C" void kernel_launch(void* const* d_in, const int* in_sizes, int n_in,
                              void* d_out, int out_size) {
    const float* x_product = (const float*)d_in[0];
    const int* pb_src = (const int*)d_in[1];
    const int* pb_dst = (const int*)d_in[2];
    const int* pc_src = (const int*)d_in[3];
    const int* pc_dst = (const int*)d_in[4];
    const int* ps_src = (const int*)d_in[5];
    const int* ps_dst = (const int*)d_in[6];
    const float* W_proj = (const float*)d_in[7];
    const float* b_proj = (const float*)d_in[8];
    const float* emb_brand = (const float*)d_in[9];
    const float* emb_cat = (const float*)d_in[10];
    const float* emb_shop = (const float*)d_in[11];
    const float* W1_l = (const float*)d_in[12];
    const float* b1_l = (const float*)d_in[13];
    const float* W1_r = (const float*)d_in[14];
    const float* W2_l = (const float*)d_in[15];
    const float* b2_l = (const float*)d_in[16];
    const float* W2_r = (const float*)d_in[17];
    float* out = (float*)d_out;

    const int nodeBlocks = (NTOT + 255) / 256;
    const int edgeBlocks = (3 * NE + 255) / 256;
    const int aggBlocks = (NTOT * 32 + 255) / 256;
    const int gemmBlocks = (NTOT + 127) / 128;

    // lazily created side stream + fork/join events (handles only, no dev mem)
    static cudaStream_t s2 = nullptr;
    static cudaEvent_t evFork = nullptr, evJoin = nullptr;
    if (!s2) {
        cudaStreamCreateWithFlags(&s2, cudaStreamNonBlocking);
        cudaEventCreateWithFlags(&evFork, cudaEventDisableTiming);
        cudaEventCreateWithFlags(&evJoin, cudaEventDisableTiming);
    }

    // fork: CSR build on s2, feature assembly on main stream
    cudaEventRecord(evFork, 0);
    cudaStreamWaitEvent(s2, evFork, 0);

    zero_deg<<<nodeBlocks, 256, 0, s2>>>();
    hist_edges<<<edgeBlocks, 256, 0, s2>>>(pb_src, pb_dst, pc_src, pc_dst, ps_src, ps_dst);
    scanA<<<NBLK_SCAN, 256, 0, s2>>>();
    scanB<<<1, 512, 0, s2>>>();
    scanC<<<nodeBlocks, 256, 0, s2>>>();
    fill_csr<<<edgeBlocks, 256, 0, s2>>>(pb_src, pb_dst, pc_src, pc_dst, ps_src, ps_dst);
    cudaEventRecord(evJoin, s2);

    proj_tc<<<(NP + 127) / 128, 256>>>(x_product, W_proj, b_proj);
    copy_emb<<<((NB + NC + NS) * H / 4 + 255) / 256, 256>>>(emb_brand, emb_cat, emb_shop);

    // join
    cudaStreamWaitEvent(0, evJoin, 0);

    // --- layer 1 ---
    aggregate<<<aggBlocks, 256>>>(0);
    finalize_tc<64, true, false><<<gemmBlocks, 256>>>(W1_r, W1_l, b1_l, out);
    // --- layer 2 ---
    aggregate<<<aggBlocks, 256>>>(1);
    finalize_tc<32, false, true><<<gemmBlocks, 256>>>(W2_r, W2_l, b2_l, out);
}